// round 1
// baseline (speedup 1.0000x reference)
#include <cuda_runtime.h>

#define G 160
#define NVOX 300000
#define GRID3 (G*G*G)

// ---------------- scratch (no allocations allowed) ----------------
__device__ __align__(16) int   g_grid[GRID3];          // voxel hash grid
__device__            int      g_cnt[27];              // per-offset pair counts
__device__ __align__(16) int   g_pair_in[27 * NVOX];   // gather source j
__device__ __align__(16) int   g_pair_out[27 * NVOX];  // scatter dest  i
__device__ __align__(16) float g_h1[NVOX * 64];        // relu(bn1(feat))
__device__ __align__(16) float g_conv1[NVOX * 128];    // conv1 out -> (in-place) relu(bn2(.))
__device__ __align__(16) float g_linT[64 * 128];       // lin_w transposed to [cin][cout]

// ---------------- setup kernels ----------------
__global__ void reset_kernel() {
    int idx = blockIdx.x * blockDim.x + threadIdx.x;
    int4* gp = (int4*)g_grid;
    const int total = GRID3 / 4;
    for (int t = idx; t < total; t += gridDim.x * blockDim.x)
        gp[t] = make_int4(-1, -1, -1, -1);
    if (idx < 27) g_cnt[idx] = 0;
}

__global__ void scatter_kernel(const int* __restrict__ pos) {
    int i = blockIdx.x * blockDim.x + threadIdx.x;
    if (i < NVOX) {
        int f = (pos[3*i] * G + pos[3*i+1]) * G + pos[3*i+2];
        g_grid[f] = i;
    }
}

// warp-aggregated rulebook build (skips center k=13; it's the identity map)
__global__ void build_pairs(const int* __restrict__ pos) {
    int i = blockIdx.x * blockDim.x + threadIdx.x;
    bool active = (i < NVOX);
    int x = 0, y = 0, z = 0;
    if (active) { x = pos[3*i]; y = pos[3*i+1]; z = pos[3*i+2]; }
    int lane = threadIdx.x & 31;
    for (int k = 0; k < 27; k++) {
        if (k == 13) continue;
        int dx = k / 9 - 1, dy = (k / 3) % 3 - 1, dz = k % 3 - 1;
        int j = -1;
        if (active) {
            int nx = x + dx, ny = y + dy, nz = z + dz;
            if (nx >= 0 && nx < G && ny >= 0 && ny < G && nz >= 0 && nz < G)
                j = g_grid[(nx * G + ny) * G + nz];
        }
        bool ok = (j >= 0);
        unsigned mask = __ballot_sync(0xffffffffu, ok);
        if (mask) {
            int leader = __ffs(mask) - 1;
            int base = 0;
            if (lane == leader) base = atomicAdd(&g_cnt[k], __popc(mask));
            base = __shfl_sync(0xffffffffu, base, leader);
            if (ok) {
                int slot = base + __popc(mask & ((1u << lane) - 1u));
                g_pair_in [k * NVOX + slot] = j;
                g_pair_out[k * NVOX + slot] = i;
            }
        }
    }
}

__global__ void transpose_lin(const float* __restrict__ lw) {
    int idx = blockIdx.x * blockDim.x + threadIdx.x;   // over 64*128
    if (idx < 64 * 128) {
        int c = idx / 128, t = idx % 128;
        g_linT[idx] = lw[t * 64 + c];                  // [cin][cout]
    }
}

// ---------------- BN(eval) + ReLU, float4 vectorized ----------------
template<int C>
__global__ void bnrelu_kernel(const float4* x, float4* y,
                              const float* __restrict__ gam, const float* __restrict__ bet,
                              const float* __restrict__ mu,  const float* __restrict__ var) {
    constexpr int C4 = C / 4;
    int idx = blockIdx.x * blockDim.x + threadIdx.x;
    if (idx >= NVOX * C4) return;
    int c = (idx % C4) * 4;
    float4 xv = x[idx];
    float4 r;
    float s0 = __ldg(gam+c+0) * rsqrtf(__ldg(var+c+0) + 1e-4f);
    float s1 = __ldg(gam+c+1) * rsqrtf(__ldg(var+c+1) + 1e-4f);
    float s2 = __ldg(gam+c+2) * rsqrtf(__ldg(var+c+2) + 1e-4f);
    float s3 = __ldg(gam+c+3) * rsqrtf(__ldg(var+c+3) + 1e-4f);
    r.x = fmaxf(0.f, (xv.x - __ldg(mu+c+0)) * s0 + __ldg(bet+c+0));
    r.y = fmaxf(0.f, (xv.y - __ldg(mu+c+1)) * s1 + __ldg(bet+c+1));
    r.z = fmaxf(0.f, (xv.z - __ldg(mu+c+2)) * s2 + __ldg(bet+c+2));
    r.w = fmaxf(0.f, (xv.w - __ldg(mu+c+3)) * s3 + __ldg(bet+c+3));
    y[idx] = r;
}

// ---------------- gathered/scattered GEMM ----------------
// Tile: 64 rows x 128 couts, BK=16, 128 threads, 8x8 microtile.
// GATHER: rows come from g_pair_in/g_pair_out segment (blockIdx.y -> offset k != 13)
// MODE: 0 = plain store, 1 = read-add-store (row unique per launch), 2 = atomicAdd
template<int CIN, bool GATHER, int MODE>
__global__ void __launch_bounds__(128)
conv_gemm(const float* __restrict__ A, const float* __restrict__ Wbase,
          float* __restrict__ out, int direct_count) {
    constexpr int BM = 64, BN = 128, BK = 16;
    __shared__ __align__(16) float As[BK * BM];
    __shared__ __align__(16) float Bs[BK * BN];
    __shared__ int ridx[BM];

    int count, seg = 0;
    const float* __restrict__ Wk;
    if (GATHER) {
        int ky = blockIdx.y;
        int k = (ky < 13) ? ky : ky + 1;
        count = g_cnt[k];
        seg = k * NVOX;
        Wk = Wbase + (size_t)k * CIN * 128;
    } else {
        count = direct_count;
        Wk = Wbase;
    }

    const int tid = threadIdx.x;
    const int tx = tid & 15;     // cout group (8 couts)
    const int ty = tid >> 4;     // row group  (8 rows)
    const int arow = tid >> 1;   // staging: row per thread-pair
    const int ahalf = tid & 1;   // staging: which 8 cin

    for (int row0 = blockIdx.x * BM; row0 < count; row0 += gridDim.x * BM) {
        if (tid < BM) {
            int r = row0 + tid;
            int j = -1;
            if (r < count) j = GATHER ? __ldg(&g_pair_in[seg + r]) : r;
            ridx[tid] = j;
        }
        __syncthreads();
        int jrow = ridx[arow];
        const float* aptr = (jrow >= 0) ? (A + (size_t)jrow * CIN + ahalf * 8) : A;

        float acc[8][8];
        #pragma unroll
        for (int i = 0; i < 8; i++)
            #pragma unroll
            for (int jj = 0; jj < 8; jj++) acc[i][jj] = 0.f;

        #pragma unroll
        for (int c0 = 0; c0 < CIN; c0 += BK) {
            // stage W chunk [BK][128]
            #pragma unroll
            for (int t = 0; t < 4; t++) {
                int idx = tid + t * 128;       // float4 index
                int kc = idx >> 5;
                int c4 = idx & 31;
                float4 v = __ldg(((const float4*)(Wk + (c0 + kc) * 128)) + c4);
                ((float4*)Bs)[idx] = v;
            }
            // stage gathered A chunk, transposed to [kc][row]
            {
                float4 v0 = make_float4(0.f,0.f,0.f,0.f), v1 = v0;
                if (jrow >= 0) {
                    v0 = __ldg((const float4*)(aptr + c0));
                    v1 = __ldg((const float4*)(aptr + c0 + 4));
                }
                int kb = ahalf * 8;
                As[(kb+0)*BM + arow] = v0.x;  As[(kb+1)*BM + arow] = v0.y;
                As[(kb+2)*BM + arow] = v0.z;  As[(kb+3)*BM + arow] = v0.w;
                As[(kb+4)*BM + arow] = v1.x;  As[(kb+5)*BM + arow] = v1.y;
                As[(kb+6)*BM + arow] = v1.z;  As[(kb+7)*BM + arow] = v1.w;
            }
            __syncthreads();
            #pragma unroll
            for (int kc = 0; kc < BK; kc++) {
                float4 a0 = *((const float4*)(As + kc*BM + ty*8));
                float4 a1 = *((const float4*)(As + kc*BM + ty*8 + 4));
                float4 b0 = *((const float4*)(Bs + kc*BN + tx*8));
                float4 b1 = *((const float4*)(Bs + kc*BN + tx*8 + 4));
                float av[8] = {a0.x,a0.y,a0.z,a0.w,a1.x,a1.y,a1.z,a1.w};
                float bv[8] = {b0.x,b0.y,b0.z,b0.w,b1.x,b1.y,b1.z,b1.w};
                #pragma unroll
                for (int i = 0; i < 8; i++)
                    #pragma unroll
                    for (int jj = 0; jj < 8; jj++)
                        acc[i][jj] += av[i] * bv[jj];
            }
            __syncthreads();
        }
        // writeback
        #pragma unroll
        for (int rr = 0; rr < 8; rr++) {
            int r = row0 + ty * 8 + rr;
            if (r < count) {
                int orow = GATHER ? __ldg(&g_pair_out[seg + r]) : r;
                float* op = out + (size_t)orow * 128 + tx * 8;
                if (MODE == 0) {
                    *((float4*)op)     = make_float4(acc[rr][0],acc[rr][1],acc[rr][2],acc[rr][3]);
                    *((float4*)(op+4)) = make_float4(acc[rr][4],acc[rr][5],acc[rr][6],acc[rr][7]);
                } else if (MODE == 1) {
                    float4 o0 = *((float4*)op), o1 = *((float4*)(op+4));
                    o0.x += acc[rr][0]; o0.y += acc[rr][1]; o0.z += acc[rr][2]; o0.w += acc[rr][3];
                    o1.x += acc[rr][4]; o1.y += acc[rr][5]; o1.z += acc[rr][6]; o1.w += acc[rr][7];
                    *((float4*)op) = o0; *((float4*)(op+4)) = o1;
                } else {
                    #pragma unroll
                    for (int c = 0; c < 8; c++) atomicAdd(op + c, acc[rr][c]);
                }
            }
        }
        __syncthreads();   // before ridx is rewritten next iteration
    }
}

// ---------------- launcher ----------------
extern "C" void kernel_launch(void* const* d_in, const int* in_sizes, int n_in,
                              void* d_out, int out_size) {
    const float* feat  = (const float*)d_in[0];
    const int*   pos   = (const int*)  d_in[1];
    const float* lin_w = (const float*)d_in[2];
    const float* bn1g  = (const float*)d_in[3];
    const float* bn1b  = (const float*)d_in[4];
    const float* bn1m  = (const float*)d_in[5];
    const float* bn1v  = (const float*)d_in[6];
    const float* W1    = (const float*)d_in[7];
    const float* bn2g  = (const float*)d_in[8];
    const float* bn2b  = (const float*)d_in[9];
    const float* bn2m  = (const float*)d_in[10];
    const float* bn2v  = (const float*)d_in[11];
    const float* W2    = (const float*)d_in[12];
    float* out = (float*)d_out;

    float *p_h1 = nullptr, *p_conv1 = nullptr, *p_linT = nullptr;
    cudaGetSymbolAddress((void**)&p_h1,    g_h1);
    cudaGetSymbolAddress((void**)&p_conv1, g_conv1);
    cudaGetSymbolAddress((void**)&p_linT,  g_linT);

    const int TILES = (NVOX + 63) / 64;

    reset_kernel   <<<2048, 256>>>();
    scatter_kernel <<<(NVOX + 255) / 256, 256>>>(pos);
    build_pairs    <<<(NVOX + 127) / 128, 128>>>(pos);
    transpose_lin  <<<(64 * 128 + 255) / 256, 256>>>(lin_w);

    // h1 = relu(bn1(feat))
    bnrelu_kernel<64><<<(NVOX * 16 + 255) / 256, 256>>>(
        (const float4*)feat, (float4*)p_h1, bn1g, bn1b, bn1m, bn1v);

    // out = feat @ lin_w^T   (also initializes d_out)
    conv_gemm<64, false, 0><<<TILES, 128>>>(feat, p_linT, out, NVOX);

    // conv1: center (identity) pass stores -> initializes g_conv1; 26 offsets atomic-add
    conv_gemm<64, false, 0><<<TILES, 128>>>(p_h1, W1 + 13 * 64 * 128, p_conv1, NVOX);
    conv_gemm<64, true,  2><<<dim3(512, 26), 128>>>(p_h1, W1, p_conv1, 0);

    // in-place relu(bn2(conv1))
    bnrelu_kernel<128><<<(NVOX * 32 + 255) / 256, 256>>>(
        (const float4*)p_conv1, (float4*)p_conv1, bn2g, bn2b, bn2m, bn2v);

    // conv2: center pass read-add-store into out; 26 offsets atomic-add into out
    conv_gemm<128, false, 1><<<TILES, 128>>>(p_conv1, W2 + 13 * 128 * 128, out, NVOX);
    conv_gemm<128, true,  2><<<dim3(512, 26), 128>>>(p_conv1, W2, out, 0);
}

// round 3
// speedup vs baseline: 1.9289x; 1.9289x over previous
#include <cuda_runtime.h>
#include <cstdint>

#define G 160
#define NVOX 300000
#define GRID3 (G*G*G)

// ---------------- scratch ----------------
__device__ __align__(16) int   g_grid[GRID3];
__device__            int      g_cnt[27];
__device__ __align__(16) int   g_pair_in[27 * NVOX];
__device__ __align__(16) int   g_pair_out[27 * NVOX];
__device__ __align__(16) float g_h1[NVOX * 64];
__device__ __align__(16) float g_conv1[NVOX * 128];

__device__ __forceinline__ float to_tf32(float x) {
    float r;
    asm("cvt.rna.tf32.f32 %0, %1;" : "=f"(r) : "f"(x));
    return r;
}
__device__ __forceinline__ void mma_tf32(float* d, const uint32_t* a, const uint32_t* b) {
    asm volatile("mma.sync.aligned.m16n8k8.row.col.f32.tf32.tf32.f32 "
                 "{%0,%1,%2,%3}, {%4,%5,%6,%7}, {%8,%9}, {%0,%1,%2,%3};"
                 : "+f"(d[0]), "+f"(d[1]), "+f"(d[2]), "+f"(d[3])
                 : "r"(a[0]), "r"(a[1]), "r"(a[2]), "r"(a[3]), "r"(b[0]), "r"(b[1]));
}

// ---------------- setup kernels ----------------
__global__ void reset_kernel() {
    int idx = blockIdx.x * blockDim.x + threadIdx.x;
    int4* gp = (int4*)g_grid;
    const int total = GRID3 / 4;
    for (int t = idx; t < total; t += gridDim.x * blockDim.x)
        gp[t] = make_int4(-1, -1, -1, -1);
    if (idx < 27) g_cnt[idx] = 0;
}

__global__ void scatter_kernel(const int* __restrict__ pos) {
    int i = blockIdx.x * blockDim.x + threadIdx.x;
    if (i < NVOX) {
        int f = (pos[3*i] * G + pos[3*i+1]) * G + pos[3*i+2];
        g_grid[f] = i;
    }
}

__global__ void build_pairs(const int* __restrict__ pos) {
    int i = blockIdx.x * blockDim.x + threadIdx.x;
    bool active = (i < NVOX);
    int x = 0, y = 0, z = 0;
    if (active) { x = pos[3*i]; y = pos[3*i+1]; z = pos[3*i+2]; }
    int lane = threadIdx.x & 31;
    for (int k = 0; k < 27; k++) {
        if (k == 13) continue;
        int dx = k / 9 - 1, dy = (k / 3) % 3 - 1, dz = k % 3 - 1;
        int j = -1;
        if (active) {
            int nx = x + dx, ny = y + dy, nz = z + dz;
            if (nx >= 0 && nx < G && ny >= 0 && ny < G && nz >= 0 && nz < G)
                j = g_grid[(nx * G + ny) * G + nz];
        }
        bool ok = (j >= 0);
        unsigned mask = __ballot_sync(0xffffffffu, ok);
        if (mask) {
            int leader = __ffs(mask) - 1;
            int base = 0;
            if (lane == leader) base = atomicAdd(&g_cnt[k], __popc(mask));
            base = __shfl_sync(0xffffffffu, base, leader);
            if (ok) {
                int slot = base + __popc(mask & ((1u << lane) - 1u));
                g_pair_in [k * NVOX + slot] = j;
                g_pair_out[k * NVOX + slot] = i;
            }
        }
    }
}

// ---------------- BN + ReLU ----------------
template<int C>
__global__ void bnrelu_kernel(const float4* x, float4* y,
                              const float* __restrict__ gam, const float* __restrict__ bet,
                              const float* __restrict__ mu,  const float* __restrict__ var) {
    constexpr int C4 = C / 4;
    int idx = blockIdx.x * blockDim.x + threadIdx.x;
    if (idx >= NVOX * C4) return;
    int c = (idx % C4) * 4;
    float4 xv = x[idx];
    float4 r;
    float s0 = __ldg(gam+c+0) * rsqrtf(__ldg(var+c+0) + 1e-4f);
    float s1 = __ldg(gam+c+1) * rsqrtf(__ldg(var+c+1) + 1e-4f);
    float s2 = __ldg(gam+c+2) * rsqrtf(__ldg(var+c+2) + 1e-4f);
    float s3 = __ldg(gam+c+3) * rsqrtf(__ldg(var+c+3) + 1e-4f);
    r.x = fmaxf(0.f, (xv.x - __ldg(mu+c+0)) * s0 + __ldg(bet+c+0));
    r.y = fmaxf(0.f, (xv.y - __ldg(mu+c+1)) * s1 + __ldg(bet+c+1));
    r.z = fmaxf(0.f, (xv.z - __ldg(mu+c+2)) * s2 + __ldg(bet+c+2));
    r.w = fmaxf(0.f, (xv.w - __ldg(mu+c+3)) * s3 + __ldg(bet+c+3));
    y[idx] = r;
}

// ---------------- HMMA tf32 gathered GEMM ----------------
// 128 rows x 128 couts per tile, K=CIN. 256 threads = 8 warps (4 row x 2 col).
// Warp computes 32 rows x 64 cols: 2 m-tiles(16) x 8 n-tiles(8), K in steps of 8.
// A staged gathered + tf32-rounded into fragment layout; B staged once per CTA.
// MODE: 0 = store, 1 = read-add-store (rows unique), 2 = atomicAdd scatter
// B(n,k) = Wsrc[k*sK + n*sN]
template<int K, bool GATHER, int MODE>
__global__ void __launch_bounds__(256)
mma_gemm(const float* __restrict__ A, const float* __restrict__ Wsrc,
         int sN, int sK, float* __restrict__ out, int direct_count) {
    constexpr int KS = K / 8;                 // k-steps
    extern __shared__ __align__(16) float smf[];
    float* sAf = smf;                         // [8 mt][KS][32 lanes][4]  = 1024*KS floats
    float* sBf = smf + 1024 * KS;             // [16 nt][KS][32 lanes][2] = 1024*KS floats
    __shared__ int ridx_in[128];
    __shared__ int ridx_out[128];

    const int tid  = threadIdx.x;
    const int wid  = tid >> 5;
    const int lane = tid & 31;
    const int wr = wid >> 1, wc = wid & 1;

    int count, seg = 0;
    const float* __restrict__ Wk = Wsrc;
    if (GATHER) {
        int k = (blockIdx.y < 13) ? blockIdx.y : blockIdx.y + 1;
        count = g_cnt[k];
        seg = k * NVOX;
        Wk = Wsrc + (size_t)k * K * 128;
    } else count = direct_count;

    // ---- stage B fragments once ----
    {
        const int total = 16 * KS * 32;
        for (int idx = tid; idx < total; idx += 256) {
            int lb = idx & 31;
            int t2 = idx >> 5;
            int ks = t2 % KS, nt = t2 / KS;
            int n = nt * 8 + (lb >> 2);
            int k = ks * 8 + (lb & 3);
            float b0 = __ldg(Wk + (size_t)k * sK + (size_t)n * sN);
            float b1 = __ldg(Wk + (size_t)(k + 4) * sK + (size_t)n * sN);
            *(float2*)(sBf + idx * 2) = make_float2(to_tf32(b0), to_tf32(b1));
        }
    }

    const int r    = tid >> 1;          // staging row 0..127
    const int half = tid & 1;           // half of K
    const int mt_s = r >> 4, r16 = r & 15, gl = r16 & 7, regm = r16 >> 3;

    for (int row0 = blockIdx.x * 128; row0 < count; row0 += gridDim.x * 128) {
        if (tid < 128) {
            int rr = row0 + tid;
            int j = -1, o = -1;
            if (rr < count) {
                j = GATHER ? __ldg(&g_pair_in [seg + rr]) : rr;
                o = GATHER ? __ldg(&g_pair_out[seg + rr]) : rr;
            }
            ridx_in[tid] = j; ridx_out[tid] = o;
        }
        __syncthreads();

        // ---- stage A fragments (gathered, tf32) ----
        {
            int j = ridx_in[r];
            const float* src = A + (size_t)(j >= 0 ? j : 0) * K + half * (K / 2);
            #pragma unroll
            for (int q = 0; q < K / 8; q++) {
                float4 v = make_float4(0.f, 0.f, 0.f, 0.f);
                if (j >= 0) v = __ldg((const float4*)(src + q * 4));
                v.x = to_tf32(v.x); v.y = to_tf32(v.y);
                v.z = to_tf32(v.z); v.w = to_tf32(v.w);
                int k0 = half * (K / 2) + q * 4;
                int ks = k0 >> 3;
                int reg = regm + (((k0 >> 2) & 1) << 1);
                float* dst = sAf + ((mt_s * KS + ks) * 32 + gl * 4) * 4 + reg;
                dst[0] = v.x; dst[4] = v.y; dst[8] = v.z; dst[12] = v.w;
            }
        }
        __syncthreads();

        // ---- compute ----
        float d[2][8][4];
        #pragma unroll
        for (int i = 0; i < 2; i++)
            #pragma unroll
            for (int j2 = 0; j2 < 8; j2++)
                #pragma unroll
                for (int q = 0; q < 4; q++) d[i][j2][q] = 0.f;

        #pragma unroll
        for (int ks = 0; ks < KS; ks++) {
            uint32_t a0[4], a1[4];
            *(float4*)a0 = *(const float4*)(sAf + (((wr*2+0)*KS + ks) * 32 + lane) * 4);
            *(float4*)a1 = *(const float4*)(sAf + (((wr*2+1)*KS + ks) * 32 + lane) * 4);
            #pragma unroll
            for (int nt = 0; nt < 8; nt++) {
                uint32_t b[2];
                *(float2*)b = *(const float2*)(sBf + (((wc*8+nt)*KS + ks) * 32 + lane) * 2);
                mma_tf32(d[0][nt], a0, b);
                mma_tf32(d[1][nt], a1, b);
            }
        }

        // ---- writeback ----
        {
            int gid = lane >> 2, tig = lane & 3;
            #pragma unroll
            for (int mt = 0; mt < 2; mt++) {
                int rbase = (wr * 2 + mt) * 16 + gid;
                #pragma unroll
                for (int h = 0; h < 2; h++) {
                    int o = ridx_out[rbase + h * 8];
                    if (o >= 0) {
                        float* op = out + (size_t)o * 128 + wc * 64 + tig * 2;
                        #pragma unroll
                        for (int nt = 0; nt < 8; nt++) {
                            float v0 = d[mt][nt][h * 2 + 0];
                            float v1 = d[mt][nt][h * 2 + 1];
                            float* p = op + nt * 8;
                            if (MODE == 0) {
                                *(float2*)p = make_float2(v0, v1);
                            } else if (MODE == 1) {
                                float2 w = *(float2*)p;
                                w.x += v0; w.y += v1;
                                *(float2*)p = w;
                            } else {
                                atomicAdd(p + 0, v0);
                                atomicAdd(p + 1, v1);
                            }
                        }
                    }
                }
            }
        }
        __syncthreads();
    }
}

// ---------------- launcher ----------------
extern "C" void kernel_launch(void* const* d_in, const int* in_sizes, int n_in,
                              void* d_out, int out_size) {
    const float* feat  = (const float*)d_in[0];
    const int*   pos   = (const int*)  d_in[1];
    const float* lin_w = (const float*)d_in[2];
    const float* bn1g  = (const float*)d_in[3];
    const float* bn1b  = (const float*)d_in[4];
    const float* bn1m  = (const float*)d_in[5];
    const float* bn1v  = (const float*)d_in[6];
    const float* W1    = (const float*)d_in[7];
    const float* bn2g  = (const float*)d_in[8];
    const float* bn2b  = (const float*)d_in[9];
    const float* bn2m  = (const float*)d_in[10];
    const float* bn2v  = (const float*)d_in[11];
    const float* W2    = (const float*)d_in[12];
    float* out = (float*)d_out;

    float *p_h1 = nullptr, *p_conv1 = nullptr;
    cudaGetSymbolAddress((void**)&p_h1,    g_h1);
    cudaGetSymbolAddress((void**)&p_conv1, g_conv1);

    const int SM64  = 2 * 1024 * 8  * 4;   // 65536
    const int SM128 = 2 * 1024 * 16 * 4;   // 131072
    cudaFuncSetAttribute(mma_gemm<64,  false, 0>, cudaFuncAttributeMaxDynamicSharedMemorySize, SM64);
    cudaFuncSetAttribute(mma_gemm<64,  true,  2>, cudaFuncAttributeMaxDynamicSharedMemorySize, SM64);
    cudaFuncSetAttribute(mma_gemm<128, false, 1>, cudaFuncAttributeMaxDynamicSharedMemorySize, SM128);
    cudaFuncSetAttribute(mma_gemm<128, true,  2>, cudaFuncAttributeMaxDynamicSharedMemorySize, SM128);

    reset_kernel   <<<2048, 256>>>();
    scatter_kernel <<<(NVOX + 255) / 256, 256>>>(pos);
    build_pairs    <<<(NVOX + 127) / 128, 128>>>(pos);

    // h1 = relu(bn1(feat))
    bnrelu_kernel<64><<<(NVOX * 16 + 255) / 256, 256>>>(
        (const float4*)feat, (float4*)p_h1, bn1g, bn1b, bn1m, bn1v);

    // skip: out = feat @ lin_w^T.  lin_w is [cout=128][cin=64] -> B(n,k): sN=64, sK=1
    mma_gemm<64, false, 0><<<1184, 256, SM64>>>(feat, lin_w, 64, 1, out, NVOX);

    // conv1 center: W1[13] is [cin][cout] -> sN=1, sK=128
    mma_gemm<64, false, 0><<<1184, 256, SM64>>>(p_h1, W1 + 13 * 64 * 128, 1, 128, p_conv1, NVOX);
    // conv1 gather: 26 offsets, atomic scatter
    mma_gemm<64, true,  2><<<dim3(44, 26), 256, SM64>>>(p_h1, W1, 1, 128, p_conv1, 0);

    // relu(bn2(conv1)) in-place
    bnrelu_kernel<128><<<(NVOX * 32 + 255) / 256, 256>>>(
        (const float4*)p_conv1, (float4*)p_conv1, bn2g, bn2b, bn2m, bn2v);

    // conv2 center: RMW into out
    mma_gemm<128, false, 1><<<592, 256, SM128>>>(p_conv1, W2 + 13 * 128 * 128, 1, 128, out, NVOX);
    // conv2 gather: 26 offsets, atomic scatter into out
    mma_gemm<128, true,  2><<<dim3(22, 26), 256, SM128>>>(p_conv1, W2, 1, 128, out, 0);
}

// round 4
// speedup vs baseline: 2.0643x; 1.0702x over previous
#include <cuda_runtime.h>
#include <cstdint>

#define G 160
#define NVOX 300000
#define GRID3 (G*G*G)

// ---------------- scratch ----------------
__device__ __align__(16) int   g_grid[GRID3];
__device__            int      g_cnt[27];
__device__ __align__(16) int   g_pair_in[27 * NVOX];
__device__ __align__(16) int   g_pair_out[27 * NVOX];
__device__ __align__(16) float g_conv1[NVOX * 128];   // raw conv1 output (pre-BN)

__device__ __forceinline__ float to_tf32(float x) {
    float r;
    asm("cvt.rna.tf32.f32 %0, %1;" : "=f"(r) : "f"(x));
    return r;
}
__device__ __forceinline__ void mma_tf32(float* d, const uint32_t* a, const uint32_t* b) {
    asm volatile("mma.sync.aligned.m16n8k8.row.col.f32.tf32.tf32.f32 "
                 "{%0,%1,%2,%3}, {%4,%5,%6,%7}, {%8,%9}, {%0,%1,%2,%3};"
                 : "+f"(d[0]), "+f"(d[1]), "+f"(d[2]), "+f"(d[3])
                 : "r"(a[0]), "r"(a[1]), "r"(a[2]), "r"(a[3]), "r"(b[0]), "r"(b[1]));
}
__device__ __forceinline__ void red_v2(float* p, float v0, float v1) {
    asm volatile("red.global.add.v2.f32 [%0], {%1, %2};"
                 :: "l"(p), "f"(v0), "f"(v1) : "memory");
}

// ---------------- setup kernels ----------------
__global__ void reset_kernel() {
    int idx = blockIdx.x * blockDim.x + threadIdx.x;
    int4* gp = (int4*)g_grid;
    const int total = GRID3 / 4;
    for (int t = idx; t < total; t += gridDim.x * blockDim.x)
        gp[t] = make_int4(-1, -1, -1, -1);
    if (idx < 27) g_cnt[idx] = 0;
}

__global__ void scatter_kernel(const int* __restrict__ pos) {
    int i = blockIdx.x * blockDim.x + threadIdx.x;
    if (i < NVOX) {
        int f = (pos[3*i] * G + pos[3*i+1]) * G + pos[3*i+2];
        g_grid[f] = i;
    }
}

__global__ void build_pairs(const int* __restrict__ pos) {
    int i = blockIdx.x * blockDim.x + threadIdx.x;
    bool active = (i < NVOX);
    int x = 0, y = 0, z = 0;
    if (active) { x = pos[3*i]; y = pos[3*i+1]; z = pos[3*i+2]; }
    int lane = threadIdx.x & 31;
    for (int k = 0; k < 27; k++) {
        if (k == 13) continue;
        int dx = k / 9 - 1, dy = (k / 3) % 3 - 1, dz = k % 3 - 1;
        int j = -1;
        if (active) {
            int nx = x + dx, ny = y + dy, nz = z + dz;
            if (nx >= 0 && nx < G && ny >= 0 && ny < G && nz >= 0 && nz < G)
                j = g_grid[(nx * G + ny) * G + nz];
        }
        bool ok = (j >= 0);
        unsigned mask = __ballot_sync(0xffffffffu, ok);
        if (mask) {
            int leader = __ffs(mask) - 1;
            int base = 0;
            if (lane == leader) base = atomicAdd(&g_cnt[k], __popc(mask));
            base = __shfl_sync(0xffffffffu, base, leader);
            if (ok) {
                int slot = base + __popc(mask & ((1u << lane) - 1u));
                g_pair_in [k * NVOX + slot] = j;
                g_pair_out[k * NVOX + slot] = i;
            }
        }
    }
}

// ---------------- HMMA tf32 gathered GEMM with fused BN+ReLU ----------------
// 128 rows x 128 couts per tile, K=CIN. 256 threads = 8 warps (4 row x 2 col).
// Warp computes 32 rows x 64 cols: 2 m-tiles(16) x 8 n-tiles(8), K steps of 8.
// BN: apply y = relu(x*scale + bias) during A staging (scale/bias in smem).
// MODE: 0 = store, 1 = read-add-store (rows unique), 2 = red.v2 scatter
// B(n,k) = Wsrc[k*sK + n*sN]
template<int K, bool GATHER, int MODE, bool BN>
__global__ void __launch_bounds__(256)
mma_gemm(const float* __restrict__ A, const float* __restrict__ Wsrc,
         int sN, int sK, float* __restrict__ out, int direct_count,
         const float* __restrict__ gam, const float* __restrict__ bet,
         const float* __restrict__ mu,  const float* __restrict__ var) {
    constexpr int KS = K / 8;                 // k-steps
    extern __shared__ __align__(16) float smf[];
    float* sAf = smf;                         // [8 mt][KS][32 lanes][4]  = 1024*KS floats
    float* sBf = smf + 1024 * KS;             // [16 nt][KS][32 lanes][2] = 1024*KS floats
    float* sScale = smf + 2048 * KS;          // [K]
    float* sBias  = sScale + K;               // [K]
    __shared__ int ridx_in[128];
    __shared__ int ridx_out[128];

    const int tid  = threadIdx.x;
    const int wid  = tid >> 5;
    const int lane = tid & 31;
    const int wr = wid >> 1, wc = wid & 1;

    int count, seg = 0;
    const float* __restrict__ Wk = Wsrc;
    if (GATHER) {
        int k = (blockIdx.y < 13) ? blockIdx.y : blockIdx.y + 1;
        count = g_cnt[k];
        seg = k * NVOX;
        Wk = Wsrc + (size_t)k * K * 128;
    } else count = direct_count;

    // ---- BN scale/bias once ----
    if (BN && tid < K) {
        float a = __ldg(gam + tid) * rsqrtf(__ldg(var + tid) + 1e-4f);
        sScale[tid] = a;
        sBias[tid]  = __ldg(bet + tid) - __ldg(mu + tid) * a;
    }

    // ---- stage B fragments once ----
    {
        const int total = 16 * KS * 32;
        for (int idx = tid; idx < total; idx += 256) {
            int lb = idx & 31;
            int t2 = idx >> 5;
            int ks = t2 % KS, nt = t2 / KS;
            int n = nt * 8 + (lb >> 2);
            int k = ks * 8 + (lb & 3);
            float b0 = __ldg(Wk + (size_t)k * sK + (size_t)n * sN);
            float b1 = __ldg(Wk + (size_t)(k + 4) * sK + (size_t)n * sN);
            *(float2*)(sBf + idx * 2) = make_float2(to_tf32(b0), to_tf32(b1));
        }
    }

    const int r    = tid >> 1;          // staging row 0..127
    const int half = tid & 1;           // half of K
    const int mt_s = r >> 4, r16 = r & 15, gl = r16 & 7, regm = r16 >> 3;

    for (int row0 = blockIdx.x * 128; row0 < count; row0 += gridDim.x * 128) {
        if (tid < 128) {
            int rr = row0 + tid;
            int j = -1, o = -1;
            if (rr < count) {
                j = GATHER ? __ldg(&g_pair_in [seg + rr]) : rr;
                o = GATHER ? __ldg(&g_pair_out[seg + rr]) : rr;
            }
            ridx_in[tid] = j; ridx_out[tid] = o;
        }
        __syncthreads();

        // ---- stage A fragments (gathered, BN+ReLU fused, tf32) ----
        {
            int j = ridx_in[r];
            const float* src = A + (size_t)(j >= 0 ? j : 0) * K + half * (K / 2);
            #pragma unroll
            for (int q = 0; q < K / 8; q++) {
                float4 v = make_float4(0.f, 0.f, 0.f, 0.f);
                int c0 = half * (K / 2) + q * 4;
                if (j >= 0) v = __ldg((const float4*)(src + q * 4));
                if (BN) {
                    float4 sc = *(const float4*)(sScale + c0);
                    float4 sb = *(const float4*)(sBias + c0);
                    v.x = fmaxf(0.f, fmaf(v.x, sc.x, sb.x));
                    v.y = fmaxf(0.f, fmaf(v.y, sc.y, sb.y));
                    v.z = fmaxf(0.f, fmaf(v.z, sc.z, sb.z));
                    v.w = fmaxf(0.f, fmaf(v.w, sc.w, sb.w));
                }
                v.x = to_tf32(v.x); v.y = to_tf32(v.y);
                v.z = to_tf32(v.z); v.w = to_tf32(v.w);
                int ks = c0 >> 3;
                int reg = regm + (((c0 >> 2) & 1) << 1);
                float* dst = sAf + ((mt_s * KS + ks) * 32 + gl * 4) * 4 + reg;
                dst[0] = v.x; dst[4] = v.y; dst[8] = v.z; dst[12] = v.w;
            }
        }
        __syncthreads();

        // ---- compute ----
        float d[2][8][4];
        #pragma unroll
        for (int i = 0; i < 2; i++)
            #pragma unroll
            for (int j2 = 0; j2 < 8; j2++)
                #pragma unroll
                for (int q = 0; q < 4; q++) d[i][j2][q] = 0.f;

        #pragma unroll
        for (int ks = 0; ks < KS; ks++) {
            uint32_t a0[4], a1[4];
            *(float4*)a0 = *(const float4*)(sAf + (((wr*2+0)*KS + ks) * 32 + lane) * 4);
            *(float4*)a1 = *(const float4*)(sAf + (((wr*2+1)*KS + ks) * 32 + lane) * 4);
            #pragma unroll
            for (int nt = 0; nt < 8; nt++) {
                uint32_t b[2];
                *(float2*)b = *(const float2*)(sBf + (((wc*8+nt)*KS + ks) * 32 + lane) * 2);
                mma_tf32(d[0][nt], a0, b);
                mma_tf32(d[1][nt], a1, b);
            }
        }

        // ---- writeback ----
        {
            int gid = lane >> 2, tig = lane & 3;
            #pragma unroll
            for (int mt = 0; mt < 2; mt++) {
                int rbase = (wr * 2 + mt) * 16 + gid;
                #pragma unroll
                for (int h = 0; h < 2; h++) {
                    int o = ridx_out[rbase + h * 8];
                    if (o >= 0) {
                        float* op = out + (size_t)o * 128 + wc * 64 + tig * 2;
                        #pragma unroll
                        for (int nt = 0; nt < 8; nt++) {
                            float v0 = d[mt][nt][h * 2 + 0];
                            float v1 = d[mt][nt][h * 2 + 1];
                            float* p = op + nt * 8;
                            if (MODE == 0) {
                                *(float2*)p = make_float2(v0, v1);
                            } else if (MODE == 1) {
                                float2 w = *(float2*)p;
                                w.x += v0; w.y += v1;
                                *(float2*)p = w;
                            } else {
                                red_v2(p, v0, v1);
                            }
                        }
                    }
                }
            }
        }
        __syncthreads();
    }
}

// ---------------- launcher ----------------
extern "C" void kernel_launch(void* const* d_in, const int* in_sizes, int n_in,
                              void* d_out, int out_size) {
    const float* feat  = (const float*)d_in[0];
    const int*   pos   = (const int*)  d_in[1];
    const float* lin_w = (const float*)d_in[2];
    const float* bn1g  = (const float*)d_in[3];
    const float* bn1b  = (const float*)d_in[4];
    const float* bn1m  = (const float*)d_in[5];
    const float* bn1v  = (const float*)d_in[6];
    const float* W1    = (const float*)d_in[7];
    const float* bn2g  = (const float*)d_in[8];
    const float* bn2b  = (const float*)d_in[9];
    const float* bn2m  = (const float*)d_in[10];
    const float* bn2v  = (const float*)d_in[11];
    const float* W2    = (const float*)d_in[12];
    float* out = (float*)d_out;

    float* p_conv1 = nullptr;
    cudaGetSymbolAddress((void**)&p_conv1, g_conv1);

    const int SM64  = 2 * 1024 * 8  * 4 + 2 * 64  * 4;   // 66048
    const int SM128 = 2 * 1024 * 16 * 4 + 2 * 128 * 4;   // 132096
    cudaFuncSetAttribute(mma_gemm<64,  false, 0, false>, cudaFuncAttributeMaxDynamicSharedMemorySize, SM64);
    cudaFuncSetAttribute(mma_gemm<64,  false, 0, true >, cudaFuncAttributeMaxDynamicSharedMemorySize, SM64);
    cudaFuncSetAttribute(mma_gemm<64,  true,  2, true >, cudaFuncAttributeMaxDynamicSharedMemorySize, SM64);
    cudaFuncSetAttribute(mma_gemm<128, false, 1, true >, cudaFuncAttributeMaxDynamicSharedMemorySize, SM128);
    cudaFuncSetAttribute(mma_gemm<128, true,  2, true >, cudaFuncAttributeMaxDynamicSharedMemorySize, SM128);

    reset_kernel   <<<2048, 256>>>();
    scatter_kernel <<<(NVOX + 255) / 256, 256>>>(pos);
    build_pairs    <<<(NVOX + 127) / 128, 128>>>(pos);

    // skip: out = feat @ lin_w^T (raw feat).  lin_w [128][64]: sN=64, sK=1
    mma_gemm<64, false, 0, false><<<1184, 256, SM64>>>(
        feat, lin_w, 64, 1, out, NVOX, nullptr, nullptr, nullptr, nullptr);

    // conv1 center: A = relu(bn1(feat)) fused.  W1[13] [cin][cout]: sN=1, sK=128
    mma_gemm<64, false, 0, true><<<1184, 256, SM64>>>(
        feat, W1 + 13 * 64 * 128, 1, 128, p_conv1, NVOX, bn1g, bn1b, bn1m, bn1v);
    // conv1 gather: 26 offsets, red.v2 scatter
    mma_gemm<64, true, 2, true><<<dim3(86, 26), 256, SM64>>>(
        feat, W1, 1, 128, p_conv1, 0, bn1g, bn1b, bn1m, bn1v);

    // conv2 center: A = relu(bn2(conv1)) fused, RMW into out
    mma_gemm<128, false, 1, true><<<592, 256, SM128>>>(
        p_conv1, W2 + 13 * 128 * 128, 1, 128, out, NVOX, bn2g, bn2b, bn2m, bn2v);
    // conv2 gather: 26 offsets, red.v2 scatter into out
    mma_gemm<128, true, 2, true><<<dim3(86, 26), 256, SM128>>>(
        p_conv1, W2, 1, 128, out, 0, bn2g, bn2b, bn2m, bn2v);
}

// round 5
// speedup vs baseline: 2.6744x; 1.2955x over previous
#include <cuda_runtime.h>
#include <cstdint>

#define G 160
#define NVOX 300000
#define GRID3 (G*G*G)

// ---------------- scratch ----------------
__device__ __align__(16) int   g_grid[GRID3];
__device__            int      g_cnt[27];
__device__            int      g_plan1[28];
__device__            int      g_plan2[28];
__device__ __align__(16) int   g_pair_in[27 * NVOX];
__device__ __align__(16) int   g_pair_out[27 * NVOX];
__device__ __align__(16) float g_conv1[NVOX * 128];   // raw conv1 output (pre-BN)

// ---------------- helpers ----------------
__device__ __forceinline__ uint32_t smem_u32(const void* p) {
    uint32_t a;
    asm("{ .reg .u64 t; cvta.to.shared.u64 t, %1; cvt.u32.u64 %0, t; }" : "=r"(a) : "l"(p));
    return a;
}
__device__ __forceinline__ float to_tf32(float x) {
    float r;
    asm("cvt.rna.tf32.f32 %0, %1;" : "=f"(r) : "f"(x));
    return r;
}
__device__ __forceinline__ void mma_tf32(float* d, const uint32_t* a, const uint32_t* b) {
    asm volatile("mma.sync.aligned.m16n8k8.row.col.f32.tf32.tf32.f32 "
                 "{%0,%1,%2,%3}, {%4,%5,%6,%7}, {%8,%9}, {%0,%1,%2,%3};"
                 : "+f"(d[0]), "+f"(d[1]), "+f"(d[2]), "+f"(d[3])
                 : "r"(a[0]), "r"(a[1]), "r"(a[2]), "r"(a[3]), "r"(b[0]), "r"(b[1]));
}
__device__ __forceinline__ void ldsm_x4(uint32_t* r, uint32_t addr) {
    asm volatile("ldmatrix.sync.aligned.m8n8.x4.shared.b16 {%0,%1,%2,%3}, [%4];"
                 : "=r"(r[0]), "=r"(r[1]), "=r"(r[2]), "=r"(r[3]) : "r"(addr));
}
__device__ __forceinline__ void ldsm_x2(uint32_t* r, uint32_t addr) {
    asm volatile("ldmatrix.sync.aligned.m8n8.x2.shared.b16 {%0,%1}, [%2];"
                 : "=r"(r[0]), "=r"(r[1]) : "r"(addr));
}
__device__ __forceinline__ void red_v2(float* p, float v0, float v1) {
    asm volatile("red.global.add.v2.f32 [%0], {%1, %2};"
                 :: "l"(p), "f"(v0), "f"(v1) : "memory");
}

// ---------------- setup kernels ----------------
__global__ void reset_kernel() {
    int idx = blockIdx.x * blockDim.x + threadIdx.x;
    int4* gp = (int4*)g_grid;
    const int total = GRID3 / 4;
    for (int t = idx; t < total; t += gridDim.x * blockDim.x)
        gp[t] = make_int4(-1, -1, -1, -1);
    if (idx < 27) g_cnt[idx] = 0;
}

__global__ void scatter_kernel(const int* __restrict__ pos) {
    int i = blockIdx.x * blockDim.x + threadIdx.x;
    if (i < NVOX) {
        int f = (pos[3*i] * G + pos[3*i+1]) * G + pos[3*i+2];
        g_grid[f] = i;
    }
}

__global__ void build_pairs(const int* __restrict__ pos) {
    int i = blockIdx.x * blockDim.x + threadIdx.x;
    bool active = (i < NVOX);
    int x = 0, y = 0, z = 0;
    if (active) { x = pos[3*i]; y = pos[3*i+1]; z = pos[3*i+2]; }
    int lane = threadIdx.x & 31;
    for (int k = 0; k < 27; k++) {
        if (k == 13) continue;
        int dx = k / 9 - 1, dy = (k / 3) % 3 - 1, dz = k % 3 - 1;
        int j = -1;
        if (active) {
            int nx = x + dx, ny = y + dy, nz = z + dz;
            if (nx >= 0 && nx < G && ny >= 0 && ny < G && nz >= 0 && nz < G)
                j = g_grid[(nx * G + ny) * G + nz];
        }
        bool ok = (j >= 0);
        unsigned mask = __ballot_sync(0xffffffffu, ok);
        if (mask) {
            int leader = __ffs(mask) - 1;
            int base = 0;
            if (lane == leader) base = atomicAdd(&g_cnt[k], __popc(mask));
            base = __shfl_sync(0xffffffffu, base, leader);
            if (ok) {
                int slot = base + __popc(mask & ((1u << lane) - 1u));
                g_pair_in [k * NVOX + slot] = j;
                g_pair_out[k * NVOX + slot] = i;
            }
        }
    }
}

__global__ void plan_kernel() {
    int acc1 = 0, acc2 = 0;
    for (int k = 0; k < 27; k++) {
        g_plan1[k] = acc1;
        g_plan2[k] = acc2;
        int t = (g_cnt[k] + 127) / 128;
        acc1 += (k == 13) ? 0 : t;
        acc2 += (k == 13) ? ((NVOX + 127) / 128) : t;
    }
    g_plan1[27] = acc1;
    g_plan2[27] = acc2;
}

// ---------------- HMMA tf32 gathered GEMM (ldmatrix + plan-balanced) ----------------
// Tile: 128 rows x 128 couts. 256 threads = 8 warps (2 row-groups x 4 col-groups):
// warp = 64 rows (4 m16 tiles) x 32 cols (4 n8 tiles). K stepped by 8.
// A/B smem: row-major, 16B chunks XOR-swizzled (c ^= row&7), read via ldmatrix.
// PLAN: 0 = dense identity rows (grid-stride, MODE must be 0)
//       1 = conv1 rulebook plan (26 offsets), 2 = conv2 plan (27, k=13 identity)
// MODE: 0 = store, 2 = red.v2 scatter.  BN fused into A staging.
template<int K, int MODE, int PLAN, bool BN, int MINCTA>
__global__ void __launch_bounds__(256, MINCTA)
mma_gemm(const float* __restrict__ A, const float* __restrict__ Wsrc,
         int sN, int sK, float* __restrict__ out,
         const float* __restrict__ gam, const float* __restrict__ bet,
         const float* __restrict__ mu,  const float* __restrict__ var) {
    constexpr int NCH = K / 4;           // 16B chunks per row
    constexpr int KS  = K / 8;           // k-steps
    constexpr int ASZ = 128 * K * 4;
    extern __shared__ __align__(128) char smem[];
    char* sA = smem;
    char* sB = smem + ASZ;
    __shared__ int   ridx_out[128];
    __shared__ float sScale[128], sBias[128];

    const int tid = threadIdx.x, wid = tid >> 5, lane = tid & 31;
    const int wr = wid >> 2, wc = wid & 3;

    if (BN && tid < K) {
        float a = __ldg(gam + tid) * rsqrtf(__ldg(var + tid) + 1e-4f);
        sScale[tid] = a;
        sBias[tid]  = __ldg(bet + tid) - __ldg(mu + tid) * a;
    }
    __syncthreads();

    const uint32_t baseA = smem_u32(sA), baseB = smem_u32(sB);

    // ldmatrix address precompute: A (x4: m0 rows0-7/ch0, m1 rows8-15/ch0, m2 rows0-7/ch1, m3 rows8-15/ch1)
    const int selA = lane >> 3;
    const int rA   = (lane & 7) + ((selA & 1) << 3);
    const int chA  = selA >> 1;
    uint32_t aBase[4]; int aXor[4];
    #pragma unroll
    for (int mt = 0; mt < 4; mt++) {
        int row = wr * 64 + mt * 16 + rA;
        aBase[mt] = baseA + row * NCH * 16;
        aXor[mt]  = row & 7;
    }
    // B (x2: m0 n-rows/ch0, m1 n-rows/ch1); lanes 16-31 mirror 0-15
    const int lb = lane & 15, selB = lb >> 3;
    uint32_t bBase[4]; int bXor[4];
    #pragma unroll
    for (int nt = 0; nt < 4; nt++) {
        int n = wc * 32 + nt * 8 + (lb & 7);
        bBase[nt] = baseB + n * NCH * 16;
        bXor[nt]  = n & 7;
    }

    // staging map: two threads per row (conflict-free STS.128 phases)
    const int srow  = wid * 16 + (lane & 15);
    const int shalf = lane >> 4;

    auto stageB = [&](const float* Wk) {
        for (int idx = tid; idx < 128 * K; idx += 256) {
            int k = idx >> 7, n = idx & 127;
            float v = to_tf32(__ldg(Wk + (size_t)k * sK + (size_t)n * sN));
            ((float*)sB)[(n * NCH + ((k >> 2) ^ (n & 7))) * 4 + (k & 3)] = v;
        }
    };

    auto processTile = [&](int row0, int cnt, int seg, bool identity) {
        int rr = row0 + srow;
        int j, o;
        if (identity) {
            j = o = (rr < cnt) ? rr : -1;
        } else {
            j = (rr < cnt) ? __ldg(&g_pair_in [seg + rr]) : -1;
            o = (rr < cnt) ? __ldg(&g_pair_out[seg + rr]) : -1;
        }
        if (shalf == 0) ridx_out[srow] = o;
        const float* src = A + (size_t)(j >= 0 ? j : 0) * K + shalf * (K / 2);
        #pragma unroll
        for (int q = 0; q < NCH / 2; q++) {
            float4 v = make_float4(0.f, 0.f, 0.f, 0.f);
            if (j >= 0) v = __ldg((const float4*)src + q);
            int c = shalf * (NCH / 2) + q;
            if (BN) {
                float4 sc = *(const float4*)(sScale + c * 4);
                float4 sb = *(const float4*)(sBias  + c * 4);
                v.x = fmaxf(0.f, fmaf(v.x, sc.x, sb.x));
                v.y = fmaxf(0.f, fmaf(v.y, sc.y, sb.y));
                v.z = fmaxf(0.f, fmaf(v.z, sc.z, sb.z));
                v.w = fmaxf(0.f, fmaf(v.w, sc.w, sb.w));
            }
            v.x = to_tf32(v.x); v.y = to_tf32(v.y);
            v.z = to_tf32(v.z); v.w = to_tf32(v.w);
            *(float4*)(sA + (srow * NCH + (c ^ (srow & 7))) * 16) = v;
        }
        __syncthreads();

        float d[4][4][4];
        #pragma unroll
        for (int mt = 0; mt < 4; mt++)
            #pragma unroll
            for (int nt = 0; nt < 4; nt++)
                #pragma unroll
                for (int q = 0; q < 4; q++) d[mt][nt][q] = 0.f;

        #pragma unroll
        for (int ks = 0; ks < KS; ks++) {
            uint32_t a[4][4], b[4][2];
            #pragma unroll
            for (int mt = 0; mt < 4; mt++)
                ldsm_x4(a[mt], aBase[mt] + (uint32_t)(((2*ks + chA) ^ aXor[mt]) << 4));
            #pragma unroll
            for (int nt = 0; nt < 4; nt++)
                ldsm_x2(b[nt], bBase[nt] + (uint32_t)(((2*ks + selB) ^ bXor[nt]) << 4));
            #pragma unroll
            for (int mt = 0; mt < 4; mt++)
                #pragma unroll
                for (int nt = 0; nt < 4; nt++)
                    mma_tf32(d[mt][nt], a[mt], b[nt]);
        }

        // writeback
        int gid = lane >> 2, tig = lane & 3;
        #pragma unroll
        for (int mt = 0; mt < 4; mt++) {
            #pragma unroll
            for (int h = 0; h < 2; h++) {
                int o2 = ridx_out[wr * 64 + mt * 16 + gid + h * 8];
                if (o2 >= 0) {
                    float* p = out + (size_t)o2 * 128 + wc * 32 + tig * 2;
                    #pragma unroll
                    for (int nt = 0; nt < 4; nt++) {
                        float v0 = d[mt][nt][h * 2 + 0];
                        float v1 = d[mt][nt][h * 2 + 1];
                        if (MODE == 0) *(float2*)(p + nt * 8) = make_float2(v0, v1);
                        else           red_v2(p + nt * 8, v0, v1);
                    }
                }
            }
        }
        __syncthreads();
    };

    if (PLAN == 0) {
        stageB(Wsrc);
        for (int row0 = blockIdx.x * 128; row0 < NVOX; row0 += gridDim.x * 128)
            processTile(row0, NVOX, 0, true);
    } else {
        const int* plan = (PLAN == 1) ? g_plan1 : g_plan2;
        int total = __ldg(&plan[27]);
        int per = (total + gridDim.x - 1) / gridDim.x;
        int lo = blockIdx.x * per;
        int hi = lo + per; if (hi > total) hi = total;
        int k = 0, curk = -1;
        for (int t = lo; t < hi; t++) {
            while (t >= __ldg(&plan[k + 1])) k++;
            if (k != curk) { stageB(Wsrc + (size_t)k * K * 128); curk = k; }
            int row0 = (t - __ldg(&plan[k])) * 128;
            bool center = (PLAN == 2) && (k == 13);
            int cnt = center ? NVOX : __ldg(&g_cnt[k]);
            processTile(row0, cnt, k * NVOX, center);
        }
    }
}

// ---------------- launcher ----------------
extern "C" void kernel_launch(void* const* d_in, const int* in_sizes, int n_in,
                              void* d_out, int out_size) {
    const float* feat  = (const float*)d_in[0];
    const int*   pos   = (const int*)  d_in[1];
    const float* lin_w = (const float*)d_in[2];
    const float* bn1g  = (const float*)d_in[3];
    const float* bn1b  = (const float*)d_in[4];
    const float* bn1m  = (const float*)d_in[5];
    const float* bn1v  = (const float*)d_in[6];
    const float* W1    = (const float*)d_in[7];
    const float* bn2g  = (const float*)d_in[8];
    const float* bn2b  = (const float*)d_in[9];
    const float* bn2m  = (const float*)d_in[10];
    const float* bn2v  = (const float*)d_in[11];
    const float* W2    = (const float*)d_in[12];
    float* out = (float*)d_out;

    float* p_conv1 = nullptr;
    cudaGetSymbolAddress((void**)&p_conv1, g_conv1);

    const int SM64  = 2 * 128 * 64  * 4;   // 65536
    const int SM128 = 2 * 128 * 128 * 4;   // 131072
    cudaFuncSetAttribute(mma_gemm<64,  0, 0, false, 2>, cudaFuncAttributeMaxDynamicSharedMemorySize, SM64);
    cudaFuncSetAttribute(mma_gemm<64,  0, 0, true,  2>, cudaFuncAttributeMaxDynamicSharedMemorySize, SM64);
    cudaFuncSetAttribute(mma_gemm<64,  2, 1, true,  2>, cudaFuncAttributeMaxDynamicSharedMemorySize, SM64);
    cudaFuncSetAttribute(mma_gemm<128, 2, 2, true,  1>, cudaFuncAttributeMaxDynamicSharedMemorySize, SM128);

    reset_kernel   <<<2048, 256>>>();
    scatter_kernel <<<(NVOX + 255) / 256, 256>>>(pos);
    build_pairs    <<<(NVOX + 127) / 128, 128>>>(pos);
    plan_kernel    <<<1, 1>>>();

    // skip: out = feat @ lin_w^T.  lin_w [128][64] -> B(n,k): sN=64, sK=1
    mma_gemm<64, 0, 0, false, 2><<<296, 256, SM64>>>(
        feat, lin_w, 64, 1, out, nullptr, nullptr, nullptr, nullptr);

    // conv1 center (dense store into g_conv1): A = relu(bn1(feat)) fused; W1[13] [cin][cout]: sN=1, sK=128
    mma_gemm<64, 0, 0, true, 2><<<296, 256, SM64>>>(
        feat, W1 + 13 * 64 * 128, 1, 128, p_conv1, bn1g, bn1b, bn1m, bn1v);

    // conv1 gather (26 offsets, red.v2 into g_conv1)
    mma_gemm<64, 2, 1, true, 2><<<296, 256, SM64>>>(
        feat, W1, 1, 128, p_conv1, bn1g, bn1b, bn1m, bn1v);

    // conv2 all 27 offsets (k=13 identity), A = relu(bn2(conv1)) fused, red.v2 into out
    mma_gemm<128, 2, 2, true, 1><<<148, 256, SM128>>>(
        p_conv1, W2, 1, 128, out, bn2g, bn2b, bn2m, bn2v);
}